// round 7
// baseline (speedup 1.0000x reference)
#include <cuda_runtime.h>
#include <cuda_fp16.h>
#include <cstdint>
#include <cstddef>

// ---------------------------------------------------------------------------
// BinaryLinear: out[M,N] = x[M,K] @ sign(W)[N,K]^T + bias[N]
// M=8192, N=4096, K=4096 (fp32 in/out).
// Round 7: crossbar-relief config — 4 warps/CTA, warp tile 64x64, 2 CTAs/SM.
//   - CTA tile 128x128 (2Mx2N warps), BK=64, 3-stage cp.async, SW128 swizzle
//   - 96 KB SMEM/CTA -> 2 CTAs resident; launch_bounds(128,2) -> 256 regs OK
//   - per CTA-kt: 64 KB ldsm + 32 KB cp.async writes = 96 B/cyc < 128 B/cyc
//   - fp16 operands (sign(W) exact in fp16), fp32 accumulate
// ---------------------------------------------------------------------------

#define BM 128
#define BN 128
#define BK 64
#define STAGES 3
#define NTHREADS 128

#define SA_BYTES (BM * BK * 2)   // 16 KB
#define SB_BYTES (BN * BK * 2)   // 16 KB
#define SMEM_TOTAL (STAGES * (SA_BYTES + SB_BYTES))   // 96 KB

// Scratch (device globals: no allocation allowed in kernel_launch)
__device__ __half g_xh[8192u * 4096u];   // x as fp16       [M,K]
__device__ __half g_wh[4096u * 4096u];   // sign(W) as fp16 [N,K]

// ---------------------- conversion kernels ---------------------------------

__global__ void cvt_x_kernel(const float4* __restrict__ x, int n4) {
    __half2* dst = reinterpret_cast<__half2*>(g_xh);
    int stride = gridDim.x * blockDim.x;
    for (int i = blockIdx.x * blockDim.x + threadIdx.x; i < n4; i += stride) {
        float4 v = x[i];
        dst[2 * i + 0] = __floats2half2_rn(v.x, v.y);
        dst[2 * i + 1] = __floats2half2_rn(v.z, v.w);
    }
}

__device__ __forceinline__ float fsign(float v) {
    return (v > 0.0f) ? 1.0f : ((v < 0.0f) ? -1.0f : 0.0f);
}

__global__ void cvt_w_kernel(const float4* __restrict__ w, int n4) {
    __half2* dst = reinterpret_cast<__half2*>(g_wh);
    int stride = gridDim.x * blockDim.x;
    for (int i = blockIdx.x * blockDim.x + threadIdx.x; i < n4; i += stride) {
        float4 v = w[i];
        dst[2 * i + 0] = __floats2half2_rn(fsign(v.x), fsign(v.y));
        dst[2 * i + 1] = __floats2half2_rn(fsign(v.z), fsign(v.w));
    }
}

// ---------------------- GEMM helpers ---------------------------------------

__device__ __forceinline__ void cp_async16(uint32_t saddr, const void* gaddr) {
    asm volatile("cp.async.cg.shared.global [%0], [%1], 16;\n"
                 :: "r"(saddr), "l"(gaddr));
}
__device__ __forceinline__ void cp_commit() {
    asm volatile("cp.async.commit_group;\n");
}
template <int N>
__device__ __forceinline__ void cp_wait() {
    asm volatile("cp.async.wait_group %0;\n" :: "n"(N));
}

__device__ __forceinline__ void ldsm4(uint32_t& r0, uint32_t& r1,
                                      uint32_t& r2, uint32_t& r3,
                                      uint32_t addr) {
    asm volatile("ldmatrix.sync.aligned.m8n8.x4.shared.b16 {%0,%1,%2,%3}, [%4];\n"
                 : "=r"(r0), "=r"(r1), "=r"(r2), "=r"(r3)
                 : "r"(addr));
}

__device__ __forceinline__ void mma16816(float* d, const uint32_t* a, const uint32_t* b) {
    asm volatile("mma.sync.aligned.m16n8k16.row.col.f32.f16.f16.f32 "
                 "{%0,%1,%2,%3}, {%4,%5,%6,%7}, {%8,%9}, {%0,%1,%2,%3};\n"
                 : "+f"(d[0]), "+f"(d[1]), "+f"(d[2]), "+f"(d[3])
                 : "r"(a[0]), "r"(a[1]), "r"(a[2]), "r"(a[3]),
                   "r"(b[0]), "r"(b[1]));
}

// issue cp.async loads for (A,B) tile kt into pipeline stage s.
// 128 threads: thread t loads full A row t (8x16B) and full B row t (8x16B).
__device__ __forceinline__ void load_tiles(int kt, int s, int NK,
                                           int bm, int bn, int K,
                                           uint32_t sA, uint32_t sB, int tid) {
    if (kt < NK) {
        int row = tid;
        int sw = row & 7;
        const __half* Ag = g_xh + (size_t)(bm + row) * K + (size_t)kt * BK;
        uint32_t da = sA + s * SA_BYTES + row * 128;
#pragma unroll
        for (int c = 0; c < 8; c++)
            cp_async16(da + ((c ^ sw) << 4), Ag + c * 8);
        const __half* Bg = g_wh + (size_t)(bn + row) * K + (size_t)kt * BK;
        uint32_t db = sB + s * SB_BYTES + row * 128;
#pragma unroll
        for (int c = 0; c < 8; c++)
            cp_async16(db + ((c ^ sw) << 4), Bg + c * 8);
    }
    cp_commit();
}

// ---------------------- GEMM kernel -----------------------------------------
// 128 threads = 4 warps laid out 2(M) x 2(N). Warp tile 64x64.
// Per 16-wide k-step: 4 A ldsm.x4, 4 B ldsm.x4, 32 mma.

__global__ __launch_bounds__(NTHREADS, 2)
void bgemm_kernel(const float* __restrict__ bias, float* __restrict__ C,
                  int M, int N, int K) {
    extern __shared__ __align__(128) unsigned char smem_raw[];
    uint32_t sbase = (uint32_t)__cvta_generic_to_shared(smem_raw);
    uint32_t sA = sbase;
    uint32_t sB = sbase + STAGES * SA_BYTES;

    int tid = threadIdx.x;
    int lane = tid & 31;
    int wid = tid >> 5;
    int wm = wid >> 1;          // 0..1 -> m offset wm*64
    int wn = wid & 1;           // 0..1 -> n offset wn*64
    int bm = blockIdx.y * BM;
    int bn = blockIdx.x * BN;

    int NK = K / BK;

#pragma unroll
    for (int s = 0; s < STAGES - 1; s++)
        load_tiles(s, s, NK, bm, bn, K, sA, sB, tid);

    float acc[4][8][4];
#pragma unroll
    for (int mi = 0; mi < 4; mi++)
#pragma unroll
        for (int ni = 0; ni < 8; ni++)
#pragma unroll
            for (int r = 0; r < 4; r++) acc[mi][ni][r] = 0.0f;

    int s = 0;
    for (int kt = 0; kt < NK; kt++) {
        cp_wait<STAGES - 2>();
        __syncthreads();   // stage s resident; oldest stage free

        load_tiles(kt + STAGES - 1, (kt + STAGES - 1) % STAGES, NK,
                   bm, bn, K, sA, sB, tid);

#pragma unroll
        for (int ks = 0; ks < BK / 16; ks++) {
            uint32_t a[4][4], b[8][2];
#pragma unroll
            for (int mi = 0; mi < 4; mi++) {
                int row = wm * 64 + mi * 16 + (lane & 15);
                int chunk = 2 * ks + (lane >> 4);
                uint32_t addr = sA + s * SA_BYTES + row * 128 + ((chunk ^ (row & 7)) << 4);
                ldsm4(a[mi][0], a[mi][1], a[mi][2], a[mi][3], addr);
            }
#pragma unroll
            for (int nj = 0; nj < 4; nj++) {
                int row = wn * 64 + nj * 16 + (lane & 7) + ((lane >> 4) << 3);
                int chunk = 2 * ks + ((lane >> 3) & 1);
                uint32_t addr = sB + s * SB_BYTES + row * 128 + ((chunk ^ (row & 7)) << 4);
                ldsm4(b[2 * nj][0], b[2 * nj][1], b[2 * nj + 1][0], b[2 * nj + 1][1], addr);
            }
#pragma unroll
            for (int mi = 0; mi < 4; mi++)
#pragma unroll
                for (int ni = 0; ni < 8; ni++)
                    mma16816(acc[mi][ni], a[mi], b[ni]);
        }
        s = (s + 1 == STAGES) ? 0 : s + 1;
    }

    cp_wait<0>();

    // epilogue: add bias, store fp32
    int crow = bm + wm * 64;
    int ccol = bn + wn * 64;
#pragma unroll
    for (int mi = 0; mi < 4; mi++) {
        int r = crow + mi * 16 + (lane >> 2);
#pragma unroll
        for (int ni = 0; ni < 8; ni++) {
            int c = ccol + ni * 8 + (lane & 3) * 2;
            float b0 = bias[c], b1 = bias[c + 1];
            float2 v0 = make_float2(acc[mi][ni][0] + b0, acc[mi][ni][1] + b1);
            float2 v1 = make_float2(acc[mi][ni][2] + b0, acc[mi][ni][3] + b1);
            *reinterpret_cast<float2*>(C + (size_t)r * N + c) = v0;
            *reinterpret_cast<float2*>(C + (size_t)(r + 8) * N + c) = v1;
        }
    }
}

// ---------------------- launch ----------------------------------------------

extern "C" void kernel_launch(void* const* d_in, const int* in_sizes, int n_in,
                              void* d_out, int out_size) {
    const float* x = (const float*)d_in[0];     // [M,K] fp32
    const float* w = (const float*)d_in[1];     // [N,K] fp32
    const float* bias = (const float*)d_in[2];  // [N]   fp32
    float* out = (float*)d_out;                 // [M,N] fp32

    int N = in_sizes[2];
    int K = in_sizes[1] / N;
    int M = in_sizes[0] / K;

    cvt_x_kernel<<<4096, 256>>>((const float4*)x, (M * K) / 4);
    cvt_w_kernel<<<4096, 256>>>((const float4*)w, (N * K) / 4);

    // Persistent attribute; harmless outside capture, inherited by capture.
    cudaFuncSetAttribute(bgemm_kernel,
                         cudaFuncAttributeMaxDynamicSharedMemorySize, SMEM_TOTAL);

    dim3 grid(N / BN, M / BM);
    bgemm_kernel<<<grid, NTHREADS, SMEM_TOTAL>>>(bias, out, M, N, K);
}

// round 8
// speedup vs baseline: 1.6186x; 1.6186x over previous
#include <cuda_runtime.h>
#include <cuda_fp16.h>
#include <cstdint>
#include <cstddef>

// ---------------------------------------------------------------------------
// BinaryLinear: out[M,N] = x[M,K] @ sign(W)[N,K]^T + bias[N]
// M=8192, N=4096, K=4096 (fp32 in/out).
// Round 8: exact R1 geometry (the empirical optimum: 128x128 CTA, 8 warps,
// 64x32 warp tile, 4-stage cp.async, 1 CTA/SM) + register-level fragment
// double-buffering to hide LDSM latency under MMA execution.
// ---------------------------------------------------------------------------

#define BM 128
#define BN 128
#define BK 64
#define STAGES 4
#define NTHREADS 256

#define SA_BYTES (BM * BK * 2)   // 16 KB
#define SB_BYTES (BN * BK * 2)   // 16 KB
#define SMEM_TOTAL (STAGES * (SA_BYTES + SB_BYTES))   // 128 KB

// Scratch (device globals: no allocation allowed in kernel_launch)
__device__ __half g_xh[8192u * 4096u];   // x as fp16       [M,K]
__device__ __half g_wh[4096u * 4096u];   // sign(W) as fp16 [N,K]

// ---------------------- conversion kernels ---------------------------------

__global__ void cvt_x_kernel(const float4* __restrict__ x, int n4) {
    __half2* dst = reinterpret_cast<__half2*>(g_xh);
    int stride = gridDim.x * blockDim.x;
    for (int i = blockIdx.x * blockDim.x + threadIdx.x; i < n4; i += stride) {
        float4 v = x[i];
        dst[2 * i + 0] = __floats2half2_rn(v.x, v.y);
        dst[2 * i + 1] = __floats2half2_rn(v.z, v.w);
    }
}

__device__ __forceinline__ float fsign(float v) {
    return (v > 0.0f) ? 1.0f : ((v < 0.0f) ? -1.0f : 0.0f);
}

__global__ void cvt_w_kernel(const float4* __restrict__ w, int n4) {
    __half2* dst = reinterpret_cast<__half2*>(g_wh);
    int stride = gridDim.x * blockDim.x;
    for (int i = blockIdx.x * blockDim.x + threadIdx.x; i < n4; i += stride) {
        float4 v = w[i];
        dst[2 * i + 0] = __floats2half2_rn(fsign(v.x), fsign(v.y));
        dst[2 * i + 1] = __floats2half2_rn(fsign(v.z), fsign(v.w));
    }
}

// ---------------------- GEMM helpers ---------------------------------------

__device__ __forceinline__ void cp_async16(uint32_t saddr, const void* gaddr) {
    asm volatile("cp.async.cg.shared.global [%0], [%1], 16;\n"
                 :: "r"(saddr), "l"(gaddr));
}
__device__ __forceinline__ void cp_commit() {
    asm volatile("cp.async.commit_group;\n");
}
template <int N>
__device__ __forceinline__ void cp_wait() {
    asm volatile("cp.async.wait_group %0;\n" :: "n"(N));
}

__device__ __forceinline__ void ldsm4(uint32_t& r0, uint32_t& r1,
                                      uint32_t& r2, uint32_t& r3,
                                      uint32_t addr) {
    asm volatile("ldmatrix.sync.aligned.m8n8.x4.shared.b16 {%0,%1,%2,%3}, [%4];\n"
                 : "=r"(r0), "=r"(r1), "=r"(r2), "=r"(r3)
                 : "r"(addr));
}

__device__ __forceinline__ void mma16816(float* d, const uint32_t* a, const uint32_t* b) {
    asm volatile("mma.sync.aligned.m16n8k16.row.col.f32.f16.f16.f32 "
                 "{%0,%1,%2,%3}, {%4,%5,%6,%7}, {%8,%9}, {%0,%1,%2,%3};\n"
                 : "+f"(d[0]), "+f"(d[1]), "+f"(d[2]), "+f"(d[3])
                 : "r"(a[0]), "r"(a[1]), "r"(a[2]), "r"(a[3]),
                   "r"(b[0]), "r"(b[1]));
}

// issue cp.async loads for (A,B) tile kt into pipeline stage s (R1 loader).
__device__ __forceinline__ void load_tiles(int kt, int s, int NK,
                                           int bm, int bn, int K,
                                           uint32_t sA, uint32_t sB,
                                           int ld_row, int ld_chunk) {
    if (kt < NK) {
        const __half* Ag = g_xh;
        const __half* Bg = g_wh;
#pragma unroll
        for (int p = 0; p < 4; p++) {
            int row = ld_row + p * 32;
            uint32_t da = sA + s * SA_BYTES + row * 128 + ((ld_chunk ^ (row & 7)) << 4);
            const void* ga = Ag + (size_t)(bm + row) * K + (size_t)kt * BK + ld_chunk * 8;
            cp_async16(da, ga);
        }
#pragma unroll
        for (int p = 0; p < 4; p++) {
            int row = ld_row + p * 32;
            uint32_t db = sB + s * SB_BYTES + row * 128 + ((ld_chunk ^ (row & 7)) << 4);
            const void* gb = Bg + (size_t)(bn + row) * K + (size_t)kt * BK + ld_chunk * 8;
            cp_async16(db, gb);
        }
    }
    cp_commit();
}

// load A+B fragments for one 16-wide k-step from stage s
__device__ __forceinline__ void load_frags(uint32_t a[4][4], uint32_t b[4][2],
                                           int ks, int s, int wm, int wn,
                                           int lane, uint32_t sA, uint32_t sB) {
#pragma unroll
    for (int mi = 0; mi < 4; mi++) {
        int row = wm * 64 + mi * 16 + (lane & 15);
        int chunk = 2 * ks + (lane >> 4);
        uint32_t addr = sA + s * SA_BYTES + row * 128 + ((chunk ^ (row & 7)) << 4);
        ldsm4(a[mi][0], a[mi][1], a[mi][2], a[mi][3], addr);
    }
#pragma unroll
    for (int nj = 0; nj < 2; nj++) {
        int row = wn * 32 + nj * 16 + (lane & 7) + ((lane >> 4) << 3);
        int chunk = 2 * ks + ((lane >> 3) & 1);
        uint32_t addr = sB + s * SB_BYTES + row * 128 + ((chunk ^ (row & 7)) << 4);
        ldsm4(b[2 * nj][0], b[2 * nj][1], b[2 * nj + 1][0], b[2 * nj + 1][1], addr);
    }
}

// ---------------------- GEMM kernel -----------------------------------------
// 256 threads = 8 warps laid out 2(M) x 4(N). Warp tile 64x32.
// Fragments double-buffered across ks so LDSM overlaps MMA.

__global__ __launch_bounds__(NTHREADS, 1)
void bgemm_kernel(const float* __restrict__ bias, float* __restrict__ C,
                  int M, int N, int K) {
    extern __shared__ __align__(128) unsigned char smem_raw[];
    uint32_t sbase = (uint32_t)__cvta_generic_to_shared(smem_raw);
    uint32_t sA = sbase;
    uint32_t sB = sbase + STAGES * SA_BYTES;

    int tid = threadIdx.x;
    int lane = tid & 31;
    int wid = tid >> 5;
    int wm = wid >> 2;          // 0..1
    int wn = wid & 3;           // 0..3
    int bm = blockIdx.y * BM;
    int bn = blockIdx.x * BN;

    int ld_row = tid >> 3;      // 0..31
    int ld_chunk = tid & 7;     // 0..7

    int NK = K / BK;

#pragma unroll
    for (int s = 0; s < STAGES - 1; s++)
        load_tiles(s, s, NK, bm, bn, K, sA, sB, ld_row, ld_chunk);

    float acc[4][4][4];
#pragma unroll
    for (int mi = 0; mi < 4; mi++)
#pragma unroll
        for (int ni = 0; ni < 4; ni++)
#pragma unroll
            for (int r = 0; r < 4; r++) acc[mi][ni][r] = 0.0f;

    uint32_t a[2][4][4], b[2][4][2];

    for (int kt = 0; kt < NK; kt++) {
        cp_wait<STAGES - 2>();
        __syncthreads();

        load_tiles(kt + STAGES - 1, (kt + STAGES - 1) % STAGES, NK,
                   bm, bn, K, sA, sB, ld_row, ld_chunk);

        int s = kt % STAGES;
        load_frags(a[0], b[0], 0, s, wm, wn, lane, sA, sB);
#pragma unroll
        for (int ks = 0; ks < BK / 16; ks++) {
            int cur = ks & 1;
            if (ks < BK / 16 - 1)
                load_frags(a[cur ^ 1], b[cur ^ 1], ks + 1, s, wm, wn, lane, sA, sB);
#pragma unroll
            for (int mi = 0; mi < 4; mi++)
#pragma unroll
                for (int ni = 0; ni < 4; ni++)
                    mma16816(acc[mi][ni], a[cur][mi], b[cur][ni]);
        }
    }

    cp_wait<0>();

    // epilogue: add bias, store fp32
    int crow = bm + wm * 64;
    int ccol = bn + wn * 32;
#pragma unroll
    for (int mi = 0; mi < 4; mi++) {
        int r = crow + mi * 16 + (lane >> 2);
#pragma unroll
        for (int ni = 0; ni < 4; ni++) {
            int c = ccol + ni * 8 + (lane & 3) * 2;
            float b0 = bias[c], b1 = bias[c + 1];
            float2 v0 = make_float2(acc[mi][ni][0] + b0, acc[mi][ni][1] + b1);
            float2 v1 = make_float2(acc[mi][ni][2] + b0, acc[mi][ni][3] + b1);
            *reinterpret_cast<float2*>(C + (size_t)r * N + c) = v0;
            *reinterpret_cast<float2*>(C + (size_t)(r + 8) * N + c) = v1;
        }
    }
}

// ---------------------- launch ----------------------------------------------

extern "C" void kernel_launch(void* const* d_in, const int* in_sizes, int n_in,
                              void* d_out, int out_size) {
    const float* x = (const float*)d_in[0];     // [M,K] fp32
    const float* w = (const float*)d_in[1];     // [N,K] fp32
    const float* bias = (const float*)d_in[2];  // [N]   fp32
    float* out = (float*)d_out;                 // [M,N] fp32

    int N = in_sizes[2];
    int K = in_sizes[1] / N;
    int M = in_sizes[0] / K;

    cvt_x_kernel<<<4096, 256>>>((const float4*)x, (M * K) / 4);
    cvt_w_kernel<<<4096, 256>>>((const float4*)w, (N * K) / 4);

    // Persistent attribute; harmless outside capture, inherited by capture.
    cudaFuncSetAttribute(bgemm_kernel,
                         cudaFuncAttributeMaxDynamicSharedMemorySize, SMEM_TOTAL);

    dim3 grid(N / BN, M / BM);
    bgemm_kernel<<<grid, NTHREADS, SMEM_TOTAL>>>(bias, out, M, N, K);
}